// round 6
// baseline (speedup 1.0000x reference)
#include <cuda_runtime.h>
#include <cuda_bf16.h>
#include <cstdint>

// ---------------------------------------------------------------------------
// CapsuleNetwork forward:
//  conv 9x9 valid + relu -> xf[64][12800]
//  wsum[k][jm] = sum_c W1[j,k,m,c]                (input-indep of conv!)
//  s1[b,jm] = (1/8) * sum_k wsum[k][jm] * xf[b,k] (routing(1) collapses)
//  v1 = squash(s1); u2 = W2 v1; v2 = routing(u2,3) -> out [64,10,16]
//
// Kernel A (fat): blocks [0,320) do conv, blocks [320,720) stream W1->wsum.
//                 The two are independent -> conv hides under the HBM stream.
// Kernel B: GEMM s1 partials over k-tiles (L2-resident operands).
// Kernel C: reduce partials, squash, digit caps + routing(3).
// ---------------------------------------------------------------------------

#define B_SZ 64
#define IN_UNITS 12800      // 32*20*20
#define KT2 32              // k per tile
#define NKT2 400            // 12800 / 32
#define CONV_BLOCKS 320

__device__ float g_xf[B_SZ * IN_UNITS];      // 3.28 MB [b][k]
__device__ float g_wsum[IN_UNITS * 64];      // 3.28 MB [k][j*8+m]
__device__ float g_part[NKT2 * B_SZ * 64];   // 6.55 MB [kt][b][jm]

// ---------------------------------------------------------------------------
// Kernel A
// ---------------------------------------------------------------------------
__global__ __launch_bounds__(256) void fused_conv_wsum_kernel(
    const float* __restrict__ x, const float* __restrict__ w,
    const float* __restrict__ bias, const float* __restrict__ W1)
{
    __shared__ float xs[784];        // conv input image
    __shared__ float wsm[32 * 81];   // all conv weights

    int bid = blockIdx.x;
    int t = threadIdx.x;

    if (bid < CONV_BLOCKS) {
        // ---- conv branch: block = (b, fifth of the (c,y,xh) space) ----
        int b = bid / 5, q = bid % 5;

        for (int i = t; i < 784; i += 256) xs[i] = x[b * 784 + i];
        for (int i = t; i < 2592; i += 256) wsm[i] = w[i];
        __syncthreads();

        int idx = q * 256 + t;            // 0..1279
        int c = idx / 40, r = idx % 40;
        int y = r >> 1, x0 = (r & 1) * 10;

        float acc[10];
        #pragma unroll
        for (int o = 0; o < 10; o++) acc[o] = 0.f;

        for (int i = 0; i < 9; i++) {
            float wr[9];
            #pragma unroll
            for (int jj = 0; jj < 9; jj++) wr[jj] = wsm[c * 81 + i * 9 + jj];
            float xr[18];
            #pragma unroll
            for (int u = 0; u < 18; u++) xr[u] = xs[(y + i) * 28 + x0 + u];
            #pragma unroll
            for (int jj = 0; jj < 9; jj++)
                #pragma unroll
                for (int o = 0; o < 10; o++)
                    acc[o] = fmaf(xr[o + jj], wr[jj], acc[o]);
        }

        float bv = bias[c];
        float* dst = &g_xf[(size_t)b * IN_UNITS + c * 400 + y * 20 + x0];
        #pragma unroll
        for (int p = 0; p < 5; p++) {
            float2 r2;
            r2.x = fmaxf(acc[p * 2 + 0] + bv, 0.f);
            r2.y = fmaxf(acc[p * 2 + 1] + bv, 0.f);
            *(float2*)&dst[p * 2] = r2;
        }
    } else {
        // ---- wsum branch: stream W1 tile, reduce over c (32) ----
        int kt = bid - CONV_BLOCKS;       // 0..399
        const float4* __restrict__ Wv = (const float4*)W1;

        #pragma unroll
        for (int j = 0; j < 8; j++) {
            size_t base = (size_t)j * 819200 + (size_t)kt * 2048;  // float4 units
            float4 v[8];
            #pragma unroll
            for (int q = 0; q < 8; q++) v[q] = Wv[base + q * 256 + t];
            #pragma unroll
            for (int q = 0; q < 8; q++) {
                float p = (v[q].x + v[q].y) + (v[q].z + v[q].w);
                p += __shfl_xor_sync(0xffffffffu, p, 1);
                p += __shfl_xor_sync(0xffffffffu, p, 2);
                p += __shfl_xor_sync(0xffffffffu, p, 4);
                if ((t & 7) == 0) {
                    int r = q * 32 + (t >> 3);            // k_local*8 + m
                    g_wsum[(size_t)(kt * KT2 + (r >> 3)) * 64 + j * 8 + (r & 7)] = p;
                }
            }
        }
    }
}

// ---------------------------------------------------------------------------
// Kernel B: s1 partial GEMM per 32-k tile. Operands L2-resident.
// 256 threads: thread = (bq in 16) x (jq in 16), 4b x 4jm outputs.
// ---------------------------------------------------------------------------
__global__ __launch_bounds__(256) void gemm_kernel()
{
    int kt = blockIdx.x;       // 0..399
    int t  = threadIdx.x;

    __shared__ float xsT[KT2 * 68];   // [kk][b]
    __shared__ float ws[KT2 * 68];    // [kk][jm]

    // load wsum tile [32][64] -> ws (row stride 68)
    {
        const float4* src = (const float4*)&g_wsum[(size_t)kt * KT2 * 64];
        #pragma unroll
        for (int q = 0; q < 2; q++) {
            int f4 = q * 256 + t;
            int kk = f4 >> 4, col = (f4 & 15) * 4;
            *(float4*)&ws[kk * 68 + col] = src[f4];
        }
    }
    // load xf tile transposed: thread (bb = t>>2, kq = t&3) loads 8 k
    {
        int bb = t >> 2, kq = t & 3;
        const float* src = &g_xf[(size_t)bb * IN_UNITS + kt * KT2 + kq * 8];
        float4 a = *(const float4*)&src[0];
        float4 c = *(const float4*)&src[4];
        int k0 = kq * 8;
        xsT[(k0 + 0) * 68 + bb] = a.x;
        xsT[(k0 + 1) * 68 + bb] = a.y;
        xsT[(k0 + 2) * 68 + bb] = a.z;
        xsT[(k0 + 3) * 68 + bb] = a.w;
        xsT[(k0 + 4) * 68 + bb] = c.x;
        xsT[(k0 + 5) * 68 + bb] = c.y;
        xsT[(k0 + 6) * 68 + bb] = c.z;
        xsT[(k0 + 7) * 68 + bb] = c.w;
    }
    __syncthreads();

    int bq = t >> 4;      // 0..15 -> b = 4*bq..
    int jq = t & 15;      // 0..15 -> jm = 4*jq..

    float a00=0.f,a01=0.f,a02=0.f,a03=0.f, a10=0.f,a11=0.f,a12=0.f,a13=0.f;
    float a20=0.f,a21=0.f,a22=0.f,a23=0.f, a30=0.f,a31=0.f,a32=0.f,a33=0.f;

    #pragma unroll
    for (int kk = 0; kk < KT2; kk++) {
        float4 xv = *(const float4*)&xsT[kk * 68 + bq * 4];
        float4 wv = *(const float4*)&ws[kk * 68 + jq * 4];
        a00 = fmaf(xv.x, wv.x, a00); a01 = fmaf(xv.x, wv.y, a01);
        a02 = fmaf(xv.x, wv.z, a02); a03 = fmaf(xv.x, wv.w, a03);
        a10 = fmaf(xv.y, wv.x, a10); a11 = fmaf(xv.y, wv.y, a11);
        a12 = fmaf(xv.y, wv.z, a12); a13 = fmaf(xv.y, wv.w, a13);
        a20 = fmaf(xv.z, wv.x, a20); a21 = fmaf(xv.z, wv.y, a21);
        a22 = fmaf(xv.z, wv.z, a22); a23 = fmaf(xv.z, wv.w, a23);
        a30 = fmaf(xv.w, wv.x, a30); a31 = fmaf(xv.w, wv.y, a31);
        a32 = fmaf(xv.w, wv.z, a32); a33 = fmaf(xv.w, wv.w, a33);
    }

    float* dst = &g_part[(size_t)kt * 4096 + (bq * 4) * 64 + jq * 4];
    *(float4*)&dst[0]   = make_float4(a00, a01, a02, a03);
    *(float4*)&dst[64]  = make_float4(a10, a11, a12, a13);
    *(float4*)&dst[128] = make_float4(a20, a21, a22, a23);
    *(float4*)&dst[192] = make_float4(a30, a31, a32, a33);
}

// ---------------------------------------------------------------------------
// Kernel C: reduce 400 partials (fixed order), squash -> v1, digit caps,
// routing(3), output. One block per batch, 512 threads.
// ---------------------------------------------------------------------------
__global__ __launch_bounds__(512) void caps2_kernel(
    const float* __restrict__ W2, float* __restrict__ out)
{
    int b = blockIdx.x;
    int t = threadIdx.x;

    __shared__ float ps[8 * 64];
    __shared__ float ss[64];
    __shared__ float v1s[64];
    __shared__ float es[80];
    __shared__ float bs[80];
    __shared__ float ds[8];

    {
        int jm = t & 63, s = t >> 6;
        const float* src = &g_part[(size_t)(s * 50) * 4096 + b * 64 + jm];
        float acc = 0.f;
        #pragma unroll
        for (int q = 0; q < 50; q++) acc += src[(size_t)q * 4096];
        ps[s * 64 + jm] = acc;
    }
    __syncthreads();
    if (t < 64) {
        float s = 0.f;
        #pragma unroll
        for (int i = 0; i < 8; i++) s += ps[i * 64 + t];
        ss[t] = s * 0.125f;
    }
    __syncthreads();
    if (t < 64) {
        int jj = t >> 3;
        float nsq = 0.f;
        #pragma unroll
        for (int mm = 0; mm < 8; mm++) { float v = ss[jj * 8 + mm]; nsq = fmaf(v, v, nsq); }
        float n = sqrtf(nsq);
        v1s[t] = ss[t] * (n / (1.f + nsq));
    }
    if (t < 80) bs[t] = 0.f;
    __syncthreads();

    bool act = (t < 160);
    int jraw = t >> 4;
    int j = (jraw < 10) ? jraw : 0;
    int m = t & 15;

    float u2r[8];
    const float4* W2v = (const float4*)W2;
    const float4* v1v = (const float4*)v1s;
    #pragma unroll
    for (int k = 0; k < 8; k++) {
        int base = ((j * 8 + k) * 16 + m) * 2;
        float4 wa = W2v[base], wb = W2v[base + 1];
        float4 va = v1v[k * 2], vb = v1v[k * 2 + 1];
        u2r[k] = wa.x * va.x + wa.y * va.y + wa.z * va.z + wa.w * va.w
               + wb.x * vb.x + wb.y * vb.y + wb.z * vb.z + wb.w * vb.w;
    }

    float v = 0.f;
    for (int it = 0; it < 3; it++) {
        if (t < 80) es[t] = expf(bs[t]);
        __syncthreads();
        if (t < 8) {
            float d = 0.f;
            #pragma unroll
            for (int jj = 0; jj < 10; jj++) d += es[jj * 8 + t];
            ds[t] = d;
        }
        __syncthreads();
        float s = 0.f;
        #pragma unroll
        for (int k = 0; k < 8; k++)
            s = fmaf(es[j * 8 + k] / ds[k], u2r[k], s);
        float p = s * s;
        p += __shfl_xor_sync(0xffffffffu, p, 1);
        p += __shfl_xor_sync(0xffffffffu, p, 2);
        p += __shfl_xor_sync(0xffffffffu, p, 4);
        p += __shfl_xor_sync(0xffffffffu, p, 8);
        float n = sqrtf(p);
        v = s * (n / (1.f + p));
        __syncthreads();
        if (it < 2) {
            #pragma unroll
            for (int k = 0; k < 8; k++) {
                float q = u2r[k] * v;
                q += __shfl_xor_sync(0xffffffffu, q, 1);
                q += __shfl_xor_sync(0xffffffffu, q, 2);
                q += __shfl_xor_sync(0xffffffffu, q, 4);
                q += __shfl_xor_sync(0xffffffffu, q, 8);
                if (act && m == 0) bs[j * 8 + k] += q;
            }
        }
        __syncthreads();
    }

    if (act) out[b * 160 + t] = v;
}

// ---------------------------------------------------------------------------
extern "C" void kernel_launch(void* const* d_in, const int* in_sizes, int n_in,
                              void* d_out, int out_size)
{
    const float* x      = (const float*)d_in[0];  // [64,1,28,28]
    const float* conv_w = (const float*)d_in[1];  // [32,1,9,9]
    const float* conv_b = (const float*)d_in[2];  // [32]
    const float* W1     = (const float*)d_in[3];  // [8,12800,8,32]
    const float* W2     = (const float*)d_in[4];  // [10,8,16,8]
    float* out = (float*)d_out;                   // [64,10,16]

    fused_conv_wsum_kernel<<<CONV_BLOCKS + NKT2, 256>>>(x, conv_w, conv_b, W1);
    gemm_kernel<<<NKT2, 256>>>();
    caps2_kernel<<<B_SZ, 512>>>(W2, out);
}